// round 13
// baseline (speedup 1.0000x reference)
#include <cuda_runtime.h>

// ---------------- problem constants ----------------
#define BATCH 32
#define HIN   256
#define WIN   256
#define H1    128
#define W1P   128
#define C1    32
#define H2    64
#define W2P   64
#define C2    64
#define FLAT  262144            // 64*64*64
#define NJ    128
#define NCH2  256               // fc1 CTA count (each covers K=1024, 4 groups of 256)

// ---------------- scratch (static device globals; no runtime alloc) ----------------
__device__ float g_conv2[(size_t)BATCH * FLAT];              // 33.5 MB
__device__ float g_part[(size_t)1024 * BATCH * NJ];          // 16 MB (1024 partials)
__device__ float g_part2[64 * BATCH * NJ];                   // 1 MB
__device__ float g_xfc[BATCH * NJ];
__device__ float g_theta[BATCH * 6];

// ---------------- packed fp32x2 helpers (bit-exact 2x fp32 FMA) ----------------
__device__ __forceinline__ unsigned long long pack2(float lo, float hi) {
    unsigned long long r;
    asm("mov.b64 %0, {%1,%2};" : "=l"(r) : "f"(lo), "f"(hi));
    return r;
}
__device__ __forceinline__ void unpack2(unsigned long long v, float& lo, float& hi) {
    asm("mov.b64 {%0,%1}, %2;" : "=f"(lo), "=f"(hi) : "l"(v));
}
__device__ __forceinline__ unsigned long long ffma2(unsigned long long a,
                                                    unsigned long long b,
                                                    unsigned long long c) {
    unsigned long long d;
    asm("fma.rn.f32x2 %0, %1, %2, %3;" : "=l"(d) : "l"(a), "l"(b), "l"(c));
    return d;
}

// dummy kernel: steers the ncu capture slot (launch #4) onto conv12. Removed
// once conv12 profile is captured.
__global__ void dummy_kernel() {}

// =====================================================================
// Fused conv1+conv2: inputs [32,256,256,3] -> g_conv2 [32,64,64,64].
// CTA = 16x16 conv2-output tile x 64 ch, 256 threads.
// conv1 phase v2: rsc FULLY unrolled (constant offsets), batches =
// 2 x 512 px (2 slots/thread) + 65-px tail (warps 0..2 only).
// =====================================================================
#define SMF_W   18432                   /* k2 relaid floats            */
#define SMF_K1  864                     /* k1 raw floats               */
#define SMF_IN  (3 * 67 * 68)           /* 13668 input floats          */
#define SMF_C14 (4 * 1089)              /* 4356 float4 conv1 tile      */
// float offsets
#define OFF_K1  (SMF_W)                               /* 18432 */
#define OFF_IN  (SMF_W + 1728)                        /* 20160 */
#define OFF_C1  (OFF_IN + SMF_IN)                     /* 33828 -> byte 135312, 16B ok */
#define SMF_TOTALF (OFF_C1 + SMF_C14 * 4)             /* 51252 floats */
#define SMF_BYTES  (SMF_TOTALF * 4)                   /* 205008 B */

__global__ __launch_bounds__(256, 1) void conv12_kernel(const float* __restrict__ in,
                                                        const float* __restrict__ k1,
                                                        const float* __restrict__ b1,
                                                        const float* __restrict__ k2,
                                                        const float* __restrict__ b2) {
    extern __shared__ __align__(16) float sm[];
    float*  wS  = sm;                       // k2 relaid
    float*  k1S = sm + OFF_K1;              // k1 raw floats
    float*  inP = sm + OFF_IN;              // 3 planes 67x68
    float4* c1S = (float4*)(sm + OFF_C1);   // 4 planes 1089

    int tid = threadIdx.x;
    int b   = blockIdx.z;
    int oh0 = blockIdx.y * 16;
    int ow0 = blockIdx.x * 16;
    int gy0 = oh0 * 4;            // raw input row origin
    int gx0 = ow0 * 4;            // raw input col origin

    // ---- k2 relayout: k2[rs][ci][oc] -> wS[((rs*32+ci)*2+half)*8+cg][4]
    for (int i = tid; i < SMF_W; i += 256) {
        int rs  = i >> 11;
        int rem = i & 2047;
        int ci  = rem >> 6;
        int oc  = rem & 63;
        int cg = oc >> 3, half = (oc >> 2) & 1, f = oc & 3;
        wS[((((rs * 32 + ci) * 2 + half) * 8 + cg) << 2) + f] = k2[i];
    }
    // ---- k1 raw copy (HWIO: ((r*3+s)*3+cin)*32 + oc)
    for (int i = tid; i < SMF_K1; i += 256) k1S[i] = k1[i];
    // ---- raw input tile 67x67x3, coalesced global order (iy, ix, c)
    for (int idx = tid; idx < 67 * 201; idx += 256) {
        int iy  = idx / 201;
        int rem = idx - iy * 201;
        int ix  = rem / 3;
        int c   = rem - ix * 3;
        int gy = gy0 + iy, gx = gx0 + ix;
        float v = 0.f;
        if (gy < HIN && gx < WIN)
            v = in[((size_t)(b * HIN + gy) * WIN + gx) * 3 + c];
        inP[c * 4556 + iy * 68 + ix] = v;
    }
    __syncthreads();

    // conv2 thread mapping (R7-proven)
    int cg   = tid & 7;
    int pset = tid >> 3;          // 0..31
    int lx   = pset & 15;
    int hi   = pset >> 4;         // 0..1; pixels ly = 2q + hi

    unsigned long long accR[8][4];
#pragma unroll
    for (int q = 0; q < 8; q++)
#pragma unroll
        for (int p = 0; p < 4; p++) accR[q][p] = 0ULL;

    const float4* wf4 = (const float4*)wS;

#pragma unroll
    for (int h = 0; h < 2; h++) {
        // ===== conv1 phase: 33x33 x 16ch. 2 full batches + 65-px tail =====
#pragma unroll 1
        for (int pp = 0; pp < 2; pp++) {
            int pA = pp * 512 + tid;      // 0..767, always valid
            int pB = pA + 256;            // 256..1023, always valid
            int yA = pA / 33, xA = pA - yA * 33;
            int yB = pB / 33, xB = pB - yB * 33;
            bool vA_ok = (2 * oh0 + yA < H1) && (2 * ow0 + xA < W1P);
            bool vB_ok = (2 * oh0 + yB < H1) && (2 * ow0 + xB < W1P);
            int bA = yA * 136 + xA * 2;
            int bB = yB * 136 + xB * 2;

            unsigned long long a1[2][8];
#pragma unroll
            for (int i = 0; i < 8; i++) { a1[0][i] = 0ULL; a1[1][i] = 0ULL; }

#pragma unroll
            for (int rsc = 0; rsc < 27; rsc++) {
                const int r   = rsc / 9;
                const int t9  = rsc - r * 9;
                const int s   = t9 / 3;
                const int cin = t9 - s * 3;
                const int roff = cin * 4556 + r * 68 + s;
                const ulonglong2* wv = (const ulonglong2*)&k1S[rsc * 32 + h * 16];
                ulonglong2 w0 = wv[0], w1 = wv[1], w2 = wv[2], w3 = wv[3];

                float vA = inP[roff + bA];
                float vB = inP[roff + bB];
                unsigned long long xA2 = pack2(vA, vA);
                unsigned long long xB2 = pack2(vB, vB);
                a1[0][0] = ffma2(xA2, w0.x, a1[0][0]);
                a1[0][1] = ffma2(xA2, w0.y, a1[0][1]);
                a1[0][2] = ffma2(xA2, w1.x, a1[0][2]);
                a1[0][3] = ffma2(xA2, w1.y, a1[0][3]);
                a1[0][4] = ffma2(xA2, w2.x, a1[0][4]);
                a1[0][5] = ffma2(xA2, w2.y, a1[0][5]);
                a1[0][6] = ffma2(xA2, w3.x, a1[0][6]);
                a1[0][7] = ffma2(xA2, w3.y, a1[0][7]);
                a1[1][0] = ffma2(xB2, w0.x, a1[1][0]);
                a1[1][1] = ffma2(xB2, w0.y, a1[1][1]);
                a1[1][2] = ffma2(xB2, w1.x, a1[1][2]);
                a1[1][3] = ffma2(xB2, w1.y, a1[1][3]);
                a1[1][4] = ffma2(xB2, w2.x, a1[1][4]);
                a1[1][5] = ffma2(xB2, w2.y, a1[1][5]);
                a1[1][6] = ffma2(xB2, w3.x, a1[1][6]);
                a1[1][7] = ffma2(xB2, w3.y, a1[1][7]);
            }

#pragma unroll
            for (int slot = 0; slot < 2; slot++) {
                bool vok = slot == 0 ? vA_ok : vB_ok;
                int  p   = slot == 0 ? pA : pB;
                float m = vok ? 1.f : 0.f;
#pragma unroll
                for (int c4 = 0; c4 < 4; c4++) {
                    float f0, f1, f2, f3;
                    unpack2(a1[slot][c4 * 2 + 0], f0, f1);
                    unpack2(a1[slot][c4 * 2 + 1], f2, f3);
                    int oc = h * 16 + c4 * 4;
                    float4 st;
                    st.x = m * fmaxf(f0 + b1[oc + 0], 0.f);
                    st.y = m * fmaxf(f1 + b1[oc + 1], 0.f);
                    st.z = m * fmaxf(f2 + b1[oc + 2], 0.f);
                    st.w = m * fmaxf(f3 + b1[oc + 3], 0.f);
                    c1S[c4 * 1089 + p] = st;
                }
            }
        }
        // tail: pixels 1024..1088 (65), only warps 0..2 participate
        if (tid < 65) {
            int pA = 1024 + tid;
            int yA = pA / 33, xA = pA - yA * 33;
            bool vA_ok = (2 * oh0 + yA < H1) && (2 * ow0 + xA < W1P);
            int bA = yA * 136 + xA * 2;

            unsigned long long a1[8];
#pragma unroll
            for (int i = 0; i < 8; i++) a1[i] = 0ULL;

#pragma unroll
            for (int rsc = 0; rsc < 27; rsc++) {
                const int r   = rsc / 9;
                const int t9  = rsc - r * 9;
                const int s   = t9 / 3;
                const int cin = t9 - s * 3;
                const int roff = cin * 4556 + r * 68 + s;
                const ulonglong2* wv = (const ulonglong2*)&k1S[rsc * 32 + h * 16];
                ulonglong2 w0 = wv[0], w1 = wv[1], w2 = wv[2], w3 = wv[3];

                float vA = inP[roff + bA];
                unsigned long long xA2 = pack2(vA, vA);
                a1[0] = ffma2(xA2, w0.x, a1[0]);
                a1[1] = ffma2(xA2, w0.y, a1[1]);
                a1[2] = ffma2(xA2, w1.x, a1[2]);
                a1[3] = ffma2(xA2, w1.y, a1[3]);
                a1[4] = ffma2(xA2, w2.x, a1[4]);
                a1[5] = ffma2(xA2, w2.y, a1[5]);
                a1[6] = ffma2(xA2, w3.x, a1[6]);
                a1[7] = ffma2(xA2, w3.y, a1[7]);
            }

            float m = vA_ok ? 1.f : 0.f;
#pragma unroll
            for (int c4 = 0; c4 < 4; c4++) {
                float f0, f1, f2, f3;
                unpack2(a1[c4 * 2 + 0], f0, f1);
                unpack2(a1[c4 * 2 + 1], f2, f3);
                int oc = h * 16 + c4 * 4;
                float4 st;
                st.x = m * fmaxf(f0 + b1[oc + 0], 0.f);
                st.y = m * fmaxf(f1 + b1[oc + 1], 0.f);
                st.z = m * fmaxf(f2 + b1[oc + 2], 0.f);
                st.w = m * fmaxf(f3 + b1[oc + 3], 0.f);
                c1S[c4 * 1089 + pA] = st;
            }
        }
        __syncthreads();

        // ================= conv2 phase over 4 local planes =================
        for (int rs = 0; rs < 9; rs++) {
            int r = rs / 3, s = rs - r * 3;
            int pbase = r * 33 + s + 2 * hi * 33 + 2 * lx;   // + 4q*33 per q
#pragma unroll 2
            for (int ci4 = 0; ci4 < 4; ci4++) {
                float4 v[8];
#pragma unroll
                for (int q = 0; q < 8; q++)
                    v[q] = c1S[ci4 * 1089 + pbase + q * 132];
#pragma unroll
                for (int cs = 0; cs < 4; cs++) {
                    int ci = h * 16 + ci4 * 4 + cs;
                    int wbase = ((rs * 32 + ci) * 2) * 8 + cg;
                    ulonglong2 wA = *(const ulonglong2*)&wf4[wbase];
                    ulonglong2 wB = *(const ulonglong2*)&wf4[wbase + 8];
#pragma unroll
                    for (int q = 0; q < 8; q++) {
                        float x = cs == 0 ? v[q].x : cs == 1 ? v[q].y
                                : cs == 2 ? v[q].z : v[q].w;
                        unsigned long long xx = pack2(x, x);
                        accR[q][0] = ffma2(xx, wA.x, accR[q][0]);
                        accR[q][1] = ffma2(xx, wA.y, accR[q][1]);
                        accR[q][2] = ffma2(xx, wB.x, accR[q][2]);
                        accR[q][3] = ffma2(xx, wB.y, accR[q][3]);
                    }
                }
            }
        }
        __syncthreads();   // c1S reused by next half
    }

    float bias[8];
#pragma unroll
    for (int p = 0; p < 8; p++) bias[p] = b2[cg * 8 + p];

#pragma unroll
    for (int q = 0; q < 8; q++) {
        int ly = 2 * q + hi;
        float* op = g_conv2 +
                    ((size_t)(b * H2 + oh0 + ly) * W2P + (ow0 + lx)) * C2 + cg * 8;
#pragma unroll
        for (int p = 0; p < 4; p++) {
            float a0, a1v;
            unpack2(accR[q][p], a0, a1v);
            float2 st;
            st.x = fmaxf(a0 + bias[2 * p + 0], 0.f);
            st.y = fmaxf(a1v + bias[2 * p + 1], 0.f);
            *(float2*)(op + 2 * p) = st;
        }
    }
}

// =====================================================================
// FC1 split-K (R7-proven): 256 CTAs, each K=1024 split into 4 groups of 256.
// Group = 64 threads: 16 jg (8 j each) x 4 bh (8 batches each).
// =====================================================================
__global__ __launch_bounds__(256) void fc1_kernel(const float* __restrict__ w1) {
    __shared__ __align__(16) float wS[8192];        // ((g*16+kk)*2+half)*64 + jg*4 + f
    __shared__ float xS[4 * 16 * 33];               // (g*16+kk)*33 + b

    int tid   = threadIdx.x;
    int chunk = blockIdx.x;
    int kb0   = chunk * 1024;

    int g  = tid >> 6;
    int t  = tid & 63;
    int jg = t & 15;
    int bh = t >> 4;            // 0..3

    unsigned long long acc[8][4];
#pragma unroll
    for (int i = 0; i < 8; i++)
#pragma unroll
        for (int p = 0; p < 4; p++) acc[i][p] = 0ULL;

    const float4* w1v = (const float4*)w1;

    for (int rnd = 0; rnd < 16; rnd++) {
        int kbase = kb0 + rnd * 16;
        {
            float4* wSv = (float4*)wS;
            for (int i = tid; i < 2048; i += 256) {
                int jj   = i & 15;
                int half = (i >> 4) & 1;
                int kkg  = i >> 5;            // 0..63
                int kk = kkg & 15, gg = kkg >> 4;
                int k  = kbase + gg * 256 + kk;
                wSv[i] = w1v[(size_t)k * 32 + jj * 2 + half];
            }
        }
        for (int i = tid; i < 2048; i += 256) {
            int kk = i & 15;
            int bb = (i >> 4) & 31;
            int gg = i >> 9;
            xS[(gg * 16 + kk) * 33 + bb] =
                g_conv2[(size_t)bb * FLAT + kbase + gg * 256 + kk];
        }
        __syncthreads();

#pragma unroll 4
        for (int kk = 0; kk < 16; kk++) {
            const float4* wb = (const float4*)wS + (g * 16 + kk) * 32;
            ulonglong2 wA = *(const ulonglong2*)&wb[jg];
            ulonglong2 wB = *(const ulonglong2*)&wb[16 + jg];
            const float* xp = &xS[(g * 16 + kk) * 33 + bh * 8];
#pragma unroll
            for (int i = 0; i < 8; i++) {
                float x = xp[i];
                unsigned long long xx = pack2(x, x);
                acc[i][0] = ffma2(xx, wA.x, acc[i][0]);
                acc[i][1] = ffma2(xx, wA.y, acc[i][1]);
                acc[i][2] = ffma2(xx, wB.x, acc[i][2]);
                acc[i][3] = ffma2(xx, wB.y, acc[i][3]);
            }
        }
        __syncthreads();
    }

    float* pp = g_part + (size_t)(chunk * 4 + g) * (BATCH * NJ);
#pragma unroll
    for (int i = 0; i < 8; i++) {
        int bb = bh * 8 + i;
        float a0, a1, a2, a3, a4, a5, a6, a7;
        unpack2(acc[i][0], a0, a1);
        unpack2(acc[i][1], a2, a3);
        unpack2(acc[i][2], a4, a5);
        unpack2(acc[i][3], a6, a7);
        float4 s0 = {a0, a1, a2, a3};
        float4 s1 = {a4, a5, a6, a7};
        float* row = pp + bb * NJ + jg * 8;
        *(float4*)(row + 0) = s0;
        *(float4*)(row + 4) = s1;
    }
}

// reduce stage A: 1024 partials -> 64 groups (16 each)
__global__ __launch_bounds__(256) void fc1_reduceA_kernel() {
    int idx = blockIdx.x * 256 + threadIdx.x;   // 0..4095
    int gy  = blockIdx.y;                       // 0..63
    float s = 0.f;
#pragma unroll
    for (int c = 0; c < 16; c++)
        s += g_part[(size_t)(gy * 16 + c) * (BATCH * NJ) + idx];
    g_part2[gy * (BATCH * NJ) + idx] = s;
}

// reduce stage B: 64 -> 1, + bias + relu
__global__ __launch_bounds__(256) void fc1_reduceB_kernel(const float* __restrict__ d1) {
    int idx = blockIdx.x * 256 + threadIdx.x;   // 0..4095
    float s = 0.f;
#pragma unroll 16
    for (int gy = 0; gy < 64; gy++)
        s += g_part2[gy * (BATCH * NJ) + idx];
    int j = idx & 127;
    g_xfc[idx] = fmaxf(s + d1[j], 0.f);
}

// theta = x @ w2 + d2
__global__ void fc2_kernel(const float* __restrict__ w2, const float* __restrict__ d2) {
    int tid = threadIdx.x;
    if (tid >= BATCH * 6) return;
    int b = tid / 6, i = tid % 6;
    float s = d2[i];
    const float* x = g_xfc + b * NJ;
#pragma unroll 8
    for (int j = 0; j < NJ; j++) s += x[j] * w2[j * 6 + i];
    g_theta[tid] = s;
}

// =====================================================================
// grid_sample: bilinear, zero padding OOB
// =====================================================================
__global__ __launch_bounds__(256) void sample_kernel(const float* __restrict__ in,
                                                     float* __restrict__ out) {
    int pid = blockIdx.x * 256 + threadIdx.x;   // < 32*256*256
    int b   = pid >> 16;
    int rem = pid & 65535;
    int y   = rem >> 8;
    int x   = rem & 255;

    const float* th = g_theta + b * 6;
    float t0 = th[0], t1 = th[1], t2 = th[2];
    float t3 = th[3], t4 = th[4], t5 = th[5];

    float X = (2.f * (float)x + 1.f) * (1.f / 256.f) - 1.f;
    float Y = (2.f * (float)y + 1.f) * (1.f / 256.f) - 1.f;
    float gx = t0 * X + t1 * Y + t2;
    float gy = t3 * X + t4 * Y + t5;
    float px = (gx + 1.f) * 128.f - 0.5f;
    float py = (gy + 1.f) * 128.f - 0.5f;

    float x0f = floorf(px), y0f = floorf(py);
    float wx1 = px - x0f, wx0 = 1.f - wx1;
    float wy1 = py - y0f, wy0 = 1.f - wy1;
    int ix0 = (int)x0f, iy0 = (int)y0f;
    int ix1 = ix0 + 1,  iy1 = iy0 + 1;

    float o0 = 0.f, o1 = 0.f, o2 = 0.f;
    const float* base = in + (size_t)b * HIN * WIN * 3;

    {
        int yi = iy0, xi = ix0; float w = wy0 * wx0;
        if (xi >= 0 && xi < WIN && yi >= 0 && yi < HIN) {
            const float* p = base + ((size_t)yi * WIN + xi) * 3;
            o0 += w * p[0]; o1 += w * p[1]; o2 += w * p[2];
        }
    }
    {
        int yi = iy0, xi = ix1; float w = wy0 * wx1;
        if (xi >= 0 && xi < WIN && yi >= 0 && yi < HIN) {
            const float* p = base + ((size_t)yi * WIN + xi) * 3;
            o0 += w * p[0]; o1 += w * p[1]; o2 += w * p[2];
        }
    }
    {
        int yi = iy1, xi = ix0; float w = wy1 * wx0;
        if (xi >= 0 && xi < WIN && yi >= 0 && yi < HIN) {
            const float* p = base + ((size_t)yi * WIN + xi) * 3;
            o0 += w * p[0]; o1 += w * p[1]; o2 += w * p[2];
        }
    }
    {
        int yi = iy1, xi = ix1; float w = wy1 * wx1;
        if (xi >= 0 && xi < WIN && yi >= 0 && yi < HIN) {
            const float* p = base + ((size_t)yi * WIN + xi) * 3;
            o0 += w * p[0]; o1 += w * p[1]; o2 += w * p[2];
        }
    }

    float* op = out + (size_t)pid * 3;
    op[0] = o0; op[1] = o1; op[2] = o2;
}

// =====================================================================
// launch
// =====================================================================
extern "C" void kernel_launch(void* const* d_in, const int* in_sizes, int n_in,
                              void* d_out, int out_size) {
    const float* inputs = (const float*)d_in[0];
    const float* k1     = (const float*)d_in[1];
    const float* b1     = (const float*)d_in[2];
    const float* k2     = (const float*)d_in[3];
    const float* b2     = (const float*)d_in[4];
    const float* w1     = (const float*)d_in[5];
    const float* d1     = (const float*)d_in[6];
    const float* w2     = (const float*)d_in[7];
    const float* d2     = (const float*)d_in[8];
    float* out = (float*)d_out;

    static int smem_set = 0;
    if (!smem_set) {
        cudaFuncSetAttribute(conv12_kernel, cudaFuncAttributeMaxDynamicSharedMemorySize,
                             SMF_BYTES);
        smem_set = 1;
    }

    // ncu-slot steering: capture lands on launch #4 -> make it conv12.
    dummy_kernel<<<1, 32>>>();
    dummy_kernel<<<1, 32>>>();
    dummy_kernel<<<1, 32>>>();

    dim3 g2(W2P / 16, H2 / 16, BATCH);   // (4, 4, 32)
    conv12_kernel<<<g2, 256, SMF_BYTES>>>(inputs, k1, b1, k2, b2);

    fc1_kernel<<<NCH2, 256>>>(w1);
    dim3 gra(16, 64);
    fc1_reduceA_kernel<<<gra, 256>>>();
    fc1_reduceB_kernel<<<16, 256>>>(d1);
    fc2_kernel<<<1, 192>>>(w2, d2);

    sample_kernel<<<(BATCH * HIN * WIN) / 256, 256>>>(inputs, out);
}

// round 16
// speedup vs baseline: 1.3364x; 1.3364x over previous
#include <cuda_runtime.h>

// ---------------- problem constants ----------------
#define BATCH 32
#define HIN   256
#define WIN   256
#define H1    128
#define W1P   128
#define C1    32
#define H2    64
#define W2P   64
#define C2    64
#define FLAT  262144            // 64*64*64
#define NJ    128
#define NCH2  256               // fc1 CTA count (each covers K=1024, 4 groups of 256)

// ---------------- scratch (static device globals; no runtime alloc) ----------------
__device__ float g_conv2[(size_t)BATCH * FLAT];              // 33.5 MB
__device__ float g_part[(size_t)1024 * BATCH * NJ];          // 16 MB (1024 partials)
__device__ float g_part2[64 * BATCH * NJ];                   // 1 MB
__device__ float g_xfc[BATCH * NJ];
__device__ float g_theta[BATCH * 6];

// ---------------- packed fp32x2 helpers (bit-exact 2x fp32 FMA) ----------------
__device__ __forceinline__ unsigned long long pack2(float lo, float hi) {
    unsigned long long r;
    asm("mov.b64 %0, {%1,%2};" : "=l"(r) : "f"(lo), "f"(hi));
    return r;
}
__device__ __forceinline__ void unpack2(unsigned long long v, float& lo, float& hi) {
    asm("mov.b64 {%0,%1}, %2;" : "=f"(lo), "=f"(hi) : "l"(v));
}
__device__ __forceinline__ unsigned long long ffma2(unsigned long long a,
                                                    unsigned long long b,
                                                    unsigned long long c) {
    unsigned long long d;
    asm("fma.rn.f32x2 %0, %1, %2, %3;" : "=l"(d) : "l"(a), "l"(b), "l"(c));
    return d;
}

// dummy kernel: steers the ncu capture slot (#4) onto fc1 this round.
__global__ void dummy_kernel() {}

// =====================================================================
// Fused conv1+conv2 v3: inputs [32,256,256,3] -> g_conv2 [32,64,64,64].
// CTA = 16x16 conv2-output tile x 64 ch, 512 threads (16 warps = 4/SMSP).
// conv1 phase: 1 px/thread, 2 full batches + 65-px tail; r/s rolled,
//   cin unrolled (incremental offsets; bounded live ranges, no spills).
// conv2 phase: R8-proven conflict-free 4px x 8ch mapping, accR[4][4].
// =====================================================================
#define SMF_W   18432                   /* k2 relaid floats            */
#define SMF_K1  864                     /* k1 raw floats               */
#define SMF_IN  (3 * 67 * 68)           /* 13668 input floats          */
#define SMF_C14 (4 * 1089)              /* 4356 float4 conv1 tile      */
// float offsets
#define OFF_K1  (SMF_W)                               /* 18432 */
#define OFF_IN  (SMF_W + 1728)                        /* 20160 */
#define OFF_C1  (OFF_IN + SMF_IN)                     /* 33828 -> byte 135312, 16B ok */
#define SMF_TOTALF (OFF_C1 + SMF_C14 * 4)             /* 51252 floats */
#define SMF_BYTES  (SMF_TOTALF * 4)                   /* 205008 B */

__global__ __launch_bounds__(512, 1) void conv12_kernel(const float* __restrict__ in,
                                                        const float* __restrict__ k1,
                                                        const float* __restrict__ b1,
                                                        const float* __restrict__ k2,
                                                        const float* __restrict__ b2) {
    extern __shared__ __align__(16) float sm[];
    float*  wS  = sm;                       // k2 relaid
    float*  k1S = sm + OFF_K1;              // k1 raw floats
    float*  inP = sm + OFF_IN;              // 3 planes 67x68
    float4* c1S = (float4*)(sm + OFF_C1);   // 4 planes 1089

    int tid = threadIdx.x;
    int b   = blockIdx.z;
    int oh0 = blockIdx.y * 16;
    int ow0 = blockIdx.x * 16;
    int gy0 = oh0 * 4;            // raw input row origin
    int gx0 = ow0 * 4;            // raw input col origin

    // ---- k2 relayout: k2[rs][ci][oc] -> wS[((rs*32+ci)*2+half)*8+cg][4]
    for (int i = tid; i < SMF_W; i += 512) {
        int rs  = i >> 11;
        int rem = i & 2047;
        int ci  = rem >> 6;
        int oc  = rem & 63;
        int cg = oc >> 3, half = (oc >> 2) & 1, f = oc & 3;
        wS[((((rs * 32 + ci) * 2 + half) * 8 + cg) << 2) + f] = k2[i];
    }
    // ---- k1 raw copy (HWIO: ((r*3+s)*3+cin)*32 + oc)
    for (int i = tid; i < SMF_K1; i += 512) k1S[i] = k1[i];
    // ---- raw input tile 67x67x3, coalesced global order (iy, ix, c)
    for (int idx = tid; idx < 67 * 201; idx += 512) {
        int iy  = idx / 201;
        int rem = idx - iy * 201;
        int ix  = rem / 3;
        int c   = rem - ix * 3;
        int gy = gy0 + iy, gx = gx0 + ix;
        float v = 0.f;
        if (gy < HIN && gx < WIN)
            v = in[((size_t)(b * HIN + gy) * WIN + gx) * 3 + c];
        inP[c * 4556 + iy * 68 + ix] = v;
    }
    __syncthreads();

    // conv2 thread mapping (R8-proven, 512 threads)
    int cg   = tid & 7;
    int pset = tid >> 3;          // 0..63
    int lx   = pset & 15;
    int gy   = pset >> 4;         // 0..3; thread pixels ly = gy*4 + q

    unsigned long long accR[4][4];
#pragma unroll
    for (int q = 0; q < 4; q++)
#pragma unroll
        for (int p = 0; p < 4; p++) accR[q][p] = 0ULL;

    const float4* wf4 = (const float4*)wS;

#pragma unroll 1
    for (int h = 0; h < 2; h++) {
        // ===== conv1 phase: 33x33 x 16ch, 1 px/thread, 2 batches + tail =====
#pragma unroll 1
        for (int bat = 0; bat < 3; bat++) {
            int p = bat * 512 + tid;
            if (p < 1089) {
                int y = p / 33, x = p - y * 33;
                bool vok = (2 * oh0 + y < H1) && (2 * ow0 + x < W1P);
                int bA = y * 136 + x * 2;

                unsigned long long a1[8];
#pragma unroll
                for (int i = 0; i < 8; i++) a1[i] = 0ULL;

                int wbase = h * 16;
#pragma unroll 1
                for (int r = 0; r < 3; r++) {
                    int ibase = bA + r * 68;
#pragma unroll 1
                    for (int s = 0; s < 3; s++) {
#pragma unroll
                        for (int cin = 0; cin < 3; cin++) {
                            const ulonglong2* wv =
                                (const ulonglong2*)&k1S[wbase + cin * 32];
                            ulonglong2 w0 = wv[0], w1 = wv[1];
                            ulonglong2 w2 = wv[2], w3 = wv[3];
                            float v = inP[ibase + s + cin * 4556];
                            unsigned long long xx = pack2(v, v);
                            a1[0] = ffma2(xx, w0.x, a1[0]);
                            a1[1] = ffma2(xx, w0.y, a1[1]);
                            a1[2] = ffma2(xx, w1.x, a1[2]);
                            a1[3] = ffma2(xx, w1.y, a1[3]);
                            a1[4] = ffma2(xx, w2.x, a1[4]);
                            a1[5] = ffma2(xx, w2.y, a1[5]);
                            a1[6] = ffma2(xx, w3.x, a1[6]);
                            a1[7] = ffma2(xx, w3.y, a1[7]);
                        }
                        wbase += 96;
                    }
                }

                float m = vok ? 1.f : 0.f;
#pragma unroll
                for (int c4 = 0; c4 < 4; c4++) {
                    float f0, f1, f2, f3;
                    unpack2(a1[c4 * 2 + 0], f0, f1);
                    unpack2(a1[c4 * 2 + 1], f2, f3);
                    int oc = h * 16 + c4 * 4;
                    float4 st;
                    st.x = m * fmaxf(f0 + b1[oc + 0], 0.f);
                    st.y = m * fmaxf(f1 + b1[oc + 1], 0.f);
                    st.z = m * fmaxf(f2 + b1[oc + 2], 0.f);
                    st.w = m * fmaxf(f3 + b1[oc + 3], 0.f);
                    c1S[c4 * 1089 + p] = st;
                }
            }
        }
        __syncthreads();

        // ================= conv2 phase over 4 local planes =================
#pragma unroll 1
        for (int rs = 0; rs < 9; rs++) {
            int r = rs / 3, s = rs - r * 3;
            int pbase = r * 33 + s + gy * 264 + 2 * lx;   // + q*66 per q
#pragma unroll 2
            for (int ci4 = 0; ci4 < 4; ci4++) {
                float4 v[4];
#pragma unroll
                for (int q = 0; q < 4; q++)
                    v[q] = c1S[ci4 * 1089 + pbase + q * 66];
#pragma unroll
                for (int cs = 0; cs < 4; cs++) {
                    int ci = h * 16 + ci4 * 4 + cs;
                    int wbase2 = ((rs * 32 + ci) * 2) * 8 + cg;
                    ulonglong2 wA = *(const ulonglong2*)&wf4[wbase2];
                    ulonglong2 wB = *(const ulonglong2*)&wf4[wbase2 + 8];
#pragma unroll
                    for (int q = 0; q < 4; q++) {
                        float x = cs == 0 ? v[q].x : cs == 1 ? v[q].y
                                : cs == 2 ? v[q].z : v[q].w;
                        unsigned long long xx = pack2(x, x);
                        accR[q][0] = ffma2(xx, wA.x, accR[q][0]);
                        accR[q][1] = ffma2(xx, wA.y, accR[q][1]);
                        accR[q][2] = ffma2(xx, wB.x, accR[q][2]);
                        accR[q][3] = ffma2(xx, wB.y, accR[q][3]);
                    }
                }
            }
        }
        __syncthreads();   // c1S reused by next half
    }

    float bias[8];
#pragma unroll
    for (int p = 0; p < 8; p++) bias[p] = b2[cg * 8 + p];

#pragma unroll
    for (int q = 0; q < 4; q++) {
        int ly = gy * 4 + q;
        float* op = g_conv2 +
                    ((size_t)(b * H2 + oh0 + ly) * W2P + (ow0 + lx)) * C2 + cg * 8;
#pragma unroll
        for (int p = 0; p < 4; p++) {
            float a0, a1v;
            unpack2(accR[q][p], a0, a1v);
            float2 st;
            st.x = fmaxf(a0 + bias[2 * p + 0], 0.f);
            st.y = fmaxf(a1v + bias[2 * p + 1], 0.f);
            *(float2*)(op + 2 * p) = st;
        }
    }
}

// =====================================================================
// FC1 split-K (R7-proven): 256 CTAs, each K=1024 split into 4 groups of 256.
// Group = 64 threads: 16 jg (8 j each) x 4 bh (8 batches each).
// =====================================================================
__global__ __launch_bounds__(256) void fc1_kernel(const float* __restrict__ w1) {
    __shared__ __align__(16) float wS[8192];        // ((g*16+kk)*2+half)*64 + jg*4 + f
    __shared__ float xS[4 * 16 * 33];               // (g*16+kk)*33 + b

    int tid   = threadIdx.x;
    int chunk = blockIdx.x;
    int kb0   = chunk * 1024;

    int g  = tid >> 6;
    int t  = tid & 63;
    int jg = t & 15;
    int bh = t >> 4;            // 0..3

    unsigned long long acc[8][4];
#pragma unroll
    for (int i = 0; i < 8; i++)
#pragma unroll
        for (int p = 0; p < 4; p++) acc[i][p] = 0ULL;

    const float4* w1v = (const float4*)w1;

    for (int rnd = 0; rnd < 16; rnd++) {
        int kbase = kb0 + rnd * 16;
        {
            float4* wSv = (float4*)wS;
            for (int i = tid; i < 2048; i += 256) {
                int jj   = i & 15;
                int half = (i >> 4) & 1;
                int kkg  = i >> 5;            // 0..63
                int kk = kkg & 15, gg = kkg >> 4;
                int k  = kbase + gg * 256 + kk;
                wSv[i] = w1v[(size_t)k * 32 + jj * 2 + half];
            }
        }
        for (int i = tid; i < 2048; i += 256) {
            int kk = i & 15;
            int bb = (i >> 4) & 31;
            int gg = i >> 9;
            xS[(gg * 16 + kk) * 33 + bb] =
                g_conv2[(size_t)bb * FLAT + kbase + gg * 256 + kk];
        }
        __syncthreads();

#pragma unroll 4
        for (int kk = 0; kk < 16; kk++) {
            const float4* wb = (const float4*)wS + (g * 16 + kk) * 32;
            ulonglong2 wA = *(const ulonglong2*)&wb[jg];
            ulonglong2 wB = *(const ulonglong2*)&wb[16 + jg];
            const float* xp = &xS[(g * 16 + kk) * 33 + bh * 8];
#pragma unroll
            for (int i = 0; i < 8; i++) {
                float x = xp[i];
                unsigned long long xx = pack2(x, x);
                acc[i][0] = ffma2(xx, wA.x, acc[i][0]);
                acc[i][1] = ffma2(xx, wA.y, acc[i][1]);
                acc[i][2] = ffma2(xx, wB.x, acc[i][2]);
                acc[i][3] = ffma2(xx, wB.y, acc[i][3]);
            }
        }
        __syncthreads();
    }

    float* pp = g_part + (size_t)(chunk * 4 + g) * (BATCH * NJ);
#pragma unroll
    for (int i = 0; i < 8; i++) {
        int bb = bh * 8 + i;
        float a0, a1, a2, a3, a4, a5, a6, a7;
        unpack2(acc[i][0], a0, a1);
        unpack2(acc[i][1], a2, a3);
        unpack2(acc[i][2], a4, a5);
        unpack2(acc[i][3], a6, a7);
        float4 s0 = {a0, a1, a2, a3};
        float4 s1 = {a4, a5, a6, a7};
        float* row = pp + bb * NJ + jg * 8;
        *(float4*)(row + 0) = s0;
        *(float4*)(row + 4) = s1;
    }
}

// reduce stage A: 1024 partials -> 64 groups (16 each)
__global__ __launch_bounds__(256) void fc1_reduceA_kernel() {
    int idx = blockIdx.x * 256 + threadIdx.x;   // 0..4095
    int gy  = blockIdx.y;                       // 0..63
    float s = 0.f;
#pragma unroll
    for (int c = 0; c < 16; c++)
        s += g_part[(size_t)(gy * 16 + c) * (BATCH * NJ) + idx];
    g_part2[gy * (BATCH * NJ) + idx] = s;
}

// reduce stage B: 64 -> 1, + bias + relu
__global__ __launch_bounds__(256) void fc1_reduceB_kernel(const float* __restrict__ d1) {
    int idx = blockIdx.x * 256 + threadIdx.x;   // 0..4095
    float s = 0.f;
#pragma unroll 16
    for (int gy = 0; gy < 64; gy++)
        s += g_part2[gy * (BATCH * NJ) + idx];
    int j = idx & 127;
    g_xfc[idx] = fmaxf(s + d1[j], 0.f);
}

// theta = x @ w2 + d2
__global__ void fc2_kernel(const float* __restrict__ w2, const float* __restrict__ d2) {
    int tid = threadIdx.x;
    if (tid >= BATCH * 6) return;
    int b = tid / 6, i = tid % 6;
    float s = d2[i];
    const float* x = g_xfc + b * NJ;
#pragma unroll 8
    for (int j = 0; j < NJ; j++) s += x[j] * w2[j * 6 + i];
    g_theta[tid] = s;
}

// =====================================================================
// grid_sample: bilinear, zero padding OOB
// =====================================================================
__global__ __launch_bounds__(256) void sample_kernel(const float* __restrict__ in,
                                                     float* __restrict__ out) {
    int pid = blockIdx.x * 256 + threadIdx.x;   // < 32*256*256
    int b   = pid >> 16;
    int rem = pid & 65535;
    int y   = rem >> 8;
    int x   = rem & 255;

    const float* th = g_theta + b * 6;
    float t0 = th[0], t1 = th[1], t2 = th[2];
    float t3 = th[3], t4 = th[4], t5 = th[5];

    float X = (2.f * (float)x + 1.f) * (1.f / 256.f) - 1.f;
    float Y = (2.f * (float)y + 1.f) * (1.f / 256.f) - 1.f;
    float gx = t0 * X + t1 * Y + t2;
    float gy = t3 * X + t4 * Y + t5;
    float px = (gx + 1.f) * 128.f - 0.5f;
    float py = (gy + 1.f) * 128.f - 0.5f;

    float x0f = floorf(px), y0f = floorf(py);
    float wx1 = px - x0f, wx0 = 1.f - wx1;
    float wy1 = py - y0f, wy0 = 1.f - wy1;
    int ix0 = (int)x0f, iy0 = (int)y0f;
    int ix1 = ix0 + 1,  iy1 = iy0 + 1;

    float o0 = 0.f, o1 = 0.f, o2 = 0.f;
    const float* base = in + (size_t)b * HIN * WIN * 3;

    {
        int yi = iy0, xi = ix0; float w = wy0 * wx0;
        if (xi >= 0 && xi < WIN && yi >= 0 && yi < HIN) {
            const float* p = base + ((size_t)yi * WIN + xi) * 3;
            o0 += w * p[0]; o1 += w * p[1]; o2 += w * p[2];
        }
    }
    {
        int yi = iy0, xi = ix1; float w = wy0 * wx1;
        if (xi >= 0 && xi < WIN && yi >= 0 && yi < HIN) {
            const float* p = base + ((size_t)yi * WIN + xi) * 3;
            o0 += w * p[0]; o1 += w * p[1]; o2 += w * p[2];
        }
    }
    {
        int yi = iy1, xi = ix0; float w = wy1 * wx0;
        if (xi >= 0 && xi < WIN && yi >= 0 && yi < HIN) {
            const float* p = base + ((size_t)yi * WIN + xi) * 3;
            o0 += w * p[0]; o1 += w * p[1]; o2 += w * p[2];
        }
    }
    {
        int yi = iy1, xi = ix1; float w = wy1 * wx1;
        if (xi >= 0 && xi < WIN && yi >= 0 && yi < HIN) {
            const float* p = base + ((size_t)yi * WIN + xi) * 3;
            o0 += w * p[0]; o1 += w * p[1]; o2 += w * p[2];
        }
    }

    float* op = out + (size_t)pid * 3;
    op[0] = o0; op[1] = o1; op[2] = o2;
}

// =====================================================================
// launch
// =====================================================================
extern "C" void kernel_launch(void* const* d_in, const int* in_sizes, int n_in,
                              void* d_out, int out_size) {
    const float* inputs = (const float*)d_in[0];
    const float* k1     = (const float*)d_in[1];
    const float* b1     = (const float*)d_in[2];
    const float* k2     = (const float*)d_in[3];
    const float* b2     = (const float*)d_in[4];
    const float* w1     = (const float*)d_in[5];
    const float* d1     = (const float*)d_in[6];
    const float* w2     = (const float*)d_in[7];
    const float* d2     = (const float*)d_in[8];
    float* out = (float*)d_out;

    static int smem_set = 0;
    if (!smem_set) {
        cudaFuncSetAttribute(conv12_kernel, cudaFuncAttributeMaxDynamicSharedMemorySize,
                             SMF_BYTES);
        smem_set = 1;
    }

    // ncu-slot steering: capture lands on launch #4 -> make it fc1.
    dummy_kernel<<<1, 32>>>();
    dummy_kernel<<<1, 32>>>();

    dim3 g2(W2P / 16, H2 / 16, BATCH);   // (4, 4, 32)
    conv12_kernel<<<g2, 512, SMF_BYTES>>>(inputs, k1, b1, k2, b2);

    fc1_kernel<<<NCH2, 256>>>(w1);
    dim3 gra(16, 64);
    fc1_reduceA_kernel<<<gra, 256>>>();
    fc1_reduceB_kernel<<<16, 256>>>(d1);
    fc2_kernel<<<1, 192>>>(w2, d2);

    sample_kernel<<<(BATCH * HIN * WIN) / 256, 256>>>(inputs, out);
}